// round 16
// baseline (speedup 1.0000x reference)
#include <cuda_runtime.h>
#include <cstdint>

// Problem constants
#define Bn  16
#define Cc  256
#define HWc 4096
#define Nq  65536
#define Kc  1024
#define ZQ_ELEMS 16777216
#define FINF __int_as_float(0x7f800000)

// -------------------------- device scratch --------------------------------
__device__ float  g_cbT[Cc * Kc];    // codebook transposed [C][K]
__device__ float  g_bnorm[Kc];       // ||c_k||^2 (R1 chain)
__device__ float  g_d2[2 * Nq];      // per-half best distance
__device__ int    g_k2[2 * Nq];      // per-half best index
__device__ int    g_idx[Nq];
__device__ double g_lpart[256];      // per-merge-block loss partial sums

// -------------------------- smem layout (bytes) ----------------------------
#define OFF_ZT 0           // float zt[256][64]          65536
#define OFF_CS 65536       // float cs[2][32][128]       32768 (double buffer)
#define OFF_BN 98304       // float bn[512]               2048
#define OFF_AS 100352      // float As[64]                 256
#define SMEM_BYTES 100608

// ---------------------------------------------------------------------------
// Prep: transpose codebook + per-code norms (identical chain to R1).
// ---------------------------------------------------------------------------
__global__ void prep_kernel(const float* __restrict__ cb) {
    int k = blockIdx.x, c = threadIdx.x;
    float v = cb[k * Cc + c];
    g_cbT[c * Kc + k] = v;
    __shared__ float sred[256];
    sred[c] = v * v;
    __syncthreads();
    for (int s = 128; s > 0; s >>= 1) {
        if (c < s) sred[c] += sred[c + s];
        __syncthreads();
    }
    if (c == 0) g_bnorm[k] = sred[0];
}

// ---------------------------------------------------------------------------
// Main: 2048 CTAs x 128 threads. CTA = (64-query tile) x (512-code half).
// bid: tile = bid >> 1, half = bid & 1 (codes half*512 .. half*512+511).
// Thread (tx,ty): queries 8*ty..8*ty+7, codes 8*tx..8*tx+7 per 128-code tile.
// 8x8 fp32 register tile, c-ascending fmaf chain (bitwise == R1 == reference).
// UNCHANGED from R14 — measured at the scalar-FFMA pipe floor.
// ---------------------------------------------------------------------------
__global__ void __launch_bounds__(128, 2) vq_main(const float* __restrict__ z) {
    extern __shared__ char smem[];
    float* zt = (float*)(smem + OFF_ZT);
    float* bn = (float*)(smem + OFF_BN);
    float* As = (float*)(smem + OFF_AS);
    float4* cs4 = (float4*)(smem + OFF_CS);        // 2 x 1024 float4

    const int tid = threadIdx.x;
    const int tx = tid & 15, ty = tid >> 4;        // tx: code lane, ty: query lane
    const int tile = blockIdx.x >> 1;
    const int half = blockIdx.x & 1;
    const int k0g  = half * 512;                   // code base for this CTA
    const int n0 = tile * 64;
    const float* zb = z + (size_t)(n0 >> 12) * (Cc * HWc) + (n0 & (HWc - 1));

    // ---- stage z [256 c][64 q] (coalesced float4) + bnorm half ----
    const float4* zb4 = (const float4*)zb;
    float4* zt4w = (float4*)zt;
    #pragma unroll
    for (int i = 0; i < 32; ++i) {
        int c = ty + 8 * i;
        zt4w[c * 16 + tx] = zb4[(size_t)c * 1024 + tx];
    }
    #pragma unroll
    for (int i = 0; i < 4; ++i) bn[tid + 128 * i] = g_bnorm[k0g + tid + 128 * i];
    __syncthreads();

    // ---- norms: exact R1 sequential fmaf chain over c ascending ----
    if (tid < 64) {
        float a = 0.f;
        #pragma unroll 8
        for (int c = 0; c < Cc; ++c) {
            float v = zt[c * 64 + tid];
            a = fmaf(v, v, a);
        }
        As[tid] = a;
    }
    __syncthreads();

    float Aqv[8];
    #pragma unroll
    for (int qi = 0; qi < 8; ++qi) Aqv[qi] = As[8 * ty + qi];

    float mv[8]; int mi[8];
    #pragma unroll
    for (int qi = 0; qi < 8; ++qi) { mv[qi] = FINF; mi[qi] = 0; }

    const float4* cbT4 = (const float4*)g_cbT;     // row c = 256 float4
    const float4* zt4 = (const float4*)zt;

    for (int kt = 0; kt < 4; ++kt) {
        const int ktg = half * 4 + kt;             // global 128-code tile id
        // ---- prefetch + store chunk 0 (32 c-rows x 128 codes) ----
        float4 pf[8];
        #pragma unroll
        for (int j = 0; j < 8; ++j) {
            int f = tid + 128 * j;                 // 0..1023
            pf[j] = cbT4[(size_t)(f >> 5) * 256 + ktg * 32 + (f & 31)];
        }
        #pragma unroll
        for (int j = 0; j < 8; ++j) {
            int f = tid + 128 * j;
            cs4[(f >> 5) * 32 + (f & 31)] = pf[j];
        }
        __syncthreads();

        float acc[8][8];
        #pragma unroll
        for (int qi = 0; qi < 8; ++qi)
            #pragma unroll
            for (int kj = 0; kj < 8; ++kj) acc[qi][kj] = 0.f;

        for (int cc = 0; cc < 8; ++cc) {           // 8 chunks x 32 c-rows
            const float4* cur = cs4 + (cc & 1) * 1024;
            if (cc < 7) {                          // prefetch next chunk
                #pragma unroll
                for (int j = 0; j < 8; ++j) {
                    int f = tid + 128 * j;
                    pf[j] = cbT4[(size_t)((cc + 1) * 32 + (f >> 5)) * 256 +
                                 ktg * 32 + (f & 31)];
                }
            }
            #pragma unroll
            for (int ck = 0; ck < 32; ++ck) {
                const int crow = cc * 32 + ck;
                float4 a0 = zt4[crow * 16 + 2 * ty];
                float4 a1 = zt4[crow * 16 + 2 * ty + 1];
                float4 b0 = cur[ck * 32 + 2 * tx];
                float4 b1 = cur[ck * 32 + 2 * tx + 1];
                float av[8] = {a0.x, a0.y, a0.z, a0.w, a1.x, a1.y, a1.z, a1.w};
                float bv[8] = {b0.x, b0.y, b0.z, b0.w, b1.x, b1.y, b1.z, b1.w};
                #pragma unroll
                for (int qi = 0; qi < 8; ++qi)
                    #pragma unroll
                    for (int kj = 0; kj < 8; ++kj)
                        acc[qi][kj] = fmaf(av[qi], bv[kj], acc[qi][kj]);
            }
            if (cc < 7) {                          // store into other buffer
                float4* nxt = cs4 + ((cc + 1) & 1) * 1024;
                #pragma unroll
                for (int j = 0; j < 8; ++j) {
                    int f = tid + 128 * j;
                    nxt[(f >> 5) * 32 + (f & 31)] = pf[j];
                }
                __syncthreads();
            }
        }

        // ---- epilogue: distances + running argmin (k ascending) ----
        float4 bn0 = ((const float4*)bn)[kt * 32 + 2 * tx];
        float4 bn1 = ((const float4*)bn)[kt * 32 + 2 * tx + 1];
        float bnv[8] = {bn0.x, bn0.y, bn0.z, bn0.w, bn1.x, bn1.y, bn1.z, bn1.w};
        #pragma unroll
        for (int qi = 0; qi < 8; ++qi)
            #pragma unroll
            for (int kj = 0; kj < 8; ++kj) {
                float d = fmaf(-2.f, acc[qi][kj], __fadd_rn(Aqv[qi], bnv[kj]));
                if (d < mv[qi]) {                   // strict < keeps lowest k
                    mv[qi] = d;
                    mi[qi] = k0g + kt * 128 + 8 * tx + kj;
                }
            }
        __syncthreads();   // before next kt reuses cs buffer 0
    }

    // ---- reduce across the 16 tx lanes (in-warp), lowest-k tie-break ----
    #pragma unroll
    for (int qi = 0; qi < 8; ++qi) {
        #pragma unroll
        for (int off = 1; off <= 8; off <<= 1) {
            float om = __shfl_xor_sync(0xffffffffu, mv[qi], off);
            int   oi = __shfl_xor_sync(0xffffffffu, mi[qi], off);
            if (om < mv[qi] || (om == mv[qi] && oi < mi[qi])) {
                mv[qi] = om; mi[qi] = oi;
            }
        }
        if (tx == 0) {
            int q = n0 + 8 * ty + qi;
            g_d2[half * Nq + q] = mv[qi];
            g_k2[half * Nq + q] = mi[qi];
        }
    }
}

// ---------------------------------------------------------------------------
// Merge the two code-half candidates (tie keeps half 0 = lower k, matching
// jnp.argmin first occurrence), write idx (int for the gather, float to the
// output if requested), and produce deterministic per-block loss partials.
// ---------------------------------------------------------------------------
__global__ void merge_kernel(float* __restrict__ out, int has_idx) {
    __shared__ double sd[256];
    int q = blockIdx.x * blockDim.x + threadIdx.x;
    float d0 = g_d2[q], d1 = g_d2[Nq + q];
    int   k0 = g_k2[q], k1 = g_k2[Nq + q];
    if (d1 < d0) { d0 = d1; k0 = k1; }
    g_idx[q] = k0;
    if (has_idx) out[ZQ_ELEMS + q] = (float)k0;
    sd[threadIdx.x] = (double)d0;
    __syncthreads();
    for (int r = 128; r > 0; r >>= 1) {
        if (threadIdx.x < r) sd[threadIdx.x] += sd[threadIdx.x + r];
        __syncthreads();
    }
    if (threadIdx.x == 0) g_lpart[blockIdx.x] = sd[0];
}

// ---------------------------------------------------------------------------
// Epilogue: blocks 0..2047 each write TWO zq_st c-planes of one batch
// (one idx load feeds both gathers; rows L1-hot); block 2048 reduces the
// 256 loss partials. Exact reference rounding throughout.
// ---------------------------------------------------------------------------
__global__ void __launch_bounds__(256) epilogue_kernel(
        float* __restrict__ out, const float* __restrict__ z, int loss_off) {
    int p = blockIdx.x;
    if (p < 2048) {
        int b = p >> 7, c0 = (p & 127) * 2;        // two planes c0, c0+1
        const float* row0 = g_cbT + (size_t)c0 * Kc;       // 4KB each, L1-hot
        const float* row1 = row0 + Kc;
        const int4*   id4 = (const int4*)(g_idx + b * HWc);
        const float4* zp0 = (const float4*)(z + ((size_t)b * Cc + c0) * HWc);
        const float4* zp1 = zp0 + (HWc / 4);
        float4* o0 = (float4*)(out + ((size_t)b * Cc + c0) * HWc);
        float4* o1 = o0 + (HWc / 4);
        #pragma unroll
        for (int i = 0; i < 4; ++i) {
            int v = threadIdx.x + 256 * i;
            int4 id = id4[v];
            float4 za = zp0[v];
            float4 zb = zp1[v];
            float4 r0, r1;
            r0.x = __fadd_rn(za.x, __fsub_rn(row0[id.x], za.x));
            r0.y = __fadd_rn(za.y, __fsub_rn(row0[id.y], za.y));
            r0.z = __fadd_rn(za.z, __fsub_rn(row0[id.z], za.z));
            r0.w = __fadd_rn(za.w, __fsub_rn(row0[id.w], za.w));
            r1.x = __fadd_rn(zb.x, __fsub_rn(row1[id.x], zb.x));
            r1.y = __fadd_rn(zb.y, __fsub_rn(row1[id.y], zb.y));
            r1.z = __fadd_rn(zb.z, __fsub_rn(row1[id.z], zb.z));
            r1.w = __fadd_rn(zb.w, __fsub_rn(row1[id.w], zb.w));
            o0[v] = r0;
            o1[v] = r1;
        }
    } else {
        if (loss_off >= 0) {
            __shared__ double sd[256];
            sd[threadIdx.x] = g_lpart[threadIdx.x];
            __syncthreads();
            for (int r = 128; r > 0; r >>= 1) {
                if (threadIdx.x < r) sd[threadIdx.x] += sd[threadIdx.x + r];
                __syncthreads();
            }
            if (threadIdx.x == 0)
                out[loss_off] = (float)(0.75 * sd[0] / (double)ZQ_ELEMS);
        }
    }
}

// ---------------------------------------------------------------------------
extern "C" void kernel_launch(void* const* d_in, const int* in_sizes, int n_in,
                              void* d_out, int out_size) {
    const float* z  = (const float*)d_in[0];   // [B,C,H,W] fp32
    const float* cb = (const float*)d_in[1];   // [K,C]     fp32
    float* out = (float*)d_out;

    cudaFuncSetAttribute(vq_main, cudaFuncAttributeMaxDynamicSharedMemorySize, SMEM_BYTES);

    int has_idx = (out_size >= ZQ_ELEMS + Nq) ? 1 : 0;
    int loss_off = -1;
    if (out_size >= ZQ_ELEMS + Nq + 1) loss_off = ZQ_ELEMS + Nq;
    else if (out_size == ZQ_ELEMS + 1) loss_off = ZQ_ELEMS;

    prep_kernel<<<Kc, 256>>>(cb);
    vq_main<<<2 * (Nq / 64), 128, SMEM_BYTES>>>(z);
    merge_kernel<<<Nq / 256, 256>>>(out, has_idx);
    epilogue_kernel<<<2049, 256>>>(out, z, loss_off);
}